// round 4
// baseline (speedup 1.0000x reference)
#include <cuda_runtime.h>
#include <cuda_bf16.h>
#include <cstdint>

// ---------------------------------------------------------------------------
// Spconv (9-tap rulebook) + LeakyReLU + BatchNorm1d, fp32-accurate via
// split-precision bf16 HMMA (mma.sync.m16n8k16):
//   x = hi + lo;  x*w ~= hi*Whi + lo*Whi + hi*Wlo   (lo*lo dropped, ~2^-18)
// Each warp computes a 16x32 D tile; CTA (8 warps) covers 128 voxels.
// A fragments built directly in registers from the gather (no smem staging).
// B fragments precomputed in exact per-lane HMMA layout.
// ---------------------------------------------------------------------------

#define FULLMASK 0xffffffffu
#define NEG_SLOPE 0.01f
#define BN_EPS 1e-5f

__device__ int      g_mask_mode;   // 0 = float32, 1 = int32, 2 = uint8/bool
__device__ double   g_sum[32];
__device__ double   g_sumsq[32];
__device__ float    g_scale[32];
__device__ float    g_bias[32];
// B fragments: frag fi = ((tap*4 + chunk)*4 + nfrag), per lane two u32 regs.
// chunk 0,1 = hi(W) for k 0-15 / 16-31 ; chunk 2,3 = lo(W) same k ranges.
__device__ uint32_t g_wb0[9 * 4 * 4 * 32];
__device__ uint32_t g_wb1[9 * 4 * 4 * 32];

// pack two floats to bf16x2: e0 -> low half, e1 -> high half
__device__ __forceinline__ uint32_t hi2(float e0, float e1) {
    uint32_t r;
    asm("cvt.rn.bf16x2.f32 %0, %1, %2;" : "=r"(r) : "f"(e1), "f"(e0));
    return r;
}
// residual pack given the hi pack
__device__ __forceinline__ uint32_t lo2(uint32_t h, float e0, float e1) {
    float h0 = __uint_as_float(h << 16);
    float h1 = __uint_as_float(h & 0xffff0000u);
    return hi2(e0 - h0, e1 - h1);
}

__device__ __forceinline__ void mma_bf16(float* d, const uint32_t* a,
                                         uint32_t b0, uint32_t b1) {
    asm volatile(
        "mma.sync.aligned.m16n8k16.row.col.f32.bf16.bf16.f32 "
        "{%0,%1,%2,%3}, {%4,%5,%6,%7}, {%8,%9}, {%0,%1,%2,%3};"
        : "+f"(d[0]), "+f"(d[1]), "+f"(d[2]), "+f"(d[3])
        : "r"(a[0]), "r"(a[1]), "r"(a[2]), "r"(a[3]), "r"(b0), "r"(b1));
}

// ---------------------------------------------------------------------------
// K0: zero BN accumulators + detect mask dtype.
// ---------------------------------------------------------------------------
__global__ void k_init(const unsigned int* __restrict__ mask_words) {
    __shared__ int s_f32, s_u8;
    int t = threadIdx.x;
    if (t == 0) { s_f32 = 0; s_u8 = 0; }
    if (t < 32) { g_sum[t] = 0.0; g_sumsq[t] = 0.0; }
    __syncthreads();
    int f32 = 0, u8 = 0;
#pragma unroll
    for (int i = 0; i < 4; i++) {
        unsigned w = mask_words[t * 4 + i];
        if (w == 0x3F800000u) f32 = 1;
        else if (w & 0xFFFFFF00u) u8 = 1;
    }
    if (f32) atomicOr(&s_f32, 1);
    if (u8)  atomicOr(&s_u8, 1);
    __syncthreads();
    if (t == 0) g_mask_mode = s_f32 ? 0 : (s_u8 ? 2 : 1);
}

// ---------------------------------------------------------------------------
// Kw: build B fragments in per-lane HMMA layout.
// B[k][n] for tap t:  k<32 -> hi(W[t][k][n]) ; chunk>=2 -> lo(W[t][k][n])
// b-frag (m16n8k16 col): reg0 = {B[kc][n], B[kc+1][n]}, reg1 = {B[kc+8][n], B[kc+9][n]}
//   kc = (lane&3)*2 + (chunk&1)*16,  n = nfrag*8 + (lane>>2)
// ---------------------------------------------------------------------------
__global__ void k_wprep(const float* __restrict__ wt) {
    for (int e = threadIdx.x; e < 9 * 4 * 4 * 32; e += blockDim.x) {
        int lane = e & 31;
        int fi   = e >> 5;
        int nf   = fi & 3;
        int j    = (fi >> 2) & 3;
        int t    = fi >> 4;
        int n    = nf * 8 + (lane >> 2);
        int kc   = (lane & 3) * 2 + (j & 1) * 16;
        float w0 = wt[(t * 32 + kc) * 32 + n];
        float w1 = wt[(t * 32 + kc + 1) * 32 + n];
        float w8 = wt[(t * 32 + kc + 8) * 32 + n];
        float w9 = wt[(t * 32 + kc + 9) * 32 + n];
        uint32_t r0, r1;
        if (j < 2) {
            r0 = hi2(w0, w1);
            r1 = hi2(w8, w9);
        } else {
            uint32_t h0 = hi2(w0, w1), h1 = hi2(w8, w9);
            r0 = lo2(h0, w0, w1);
            r1 = lo2(h1, w8, w9);
        }
        g_wb0[e] = r0;
        g_wb1[e] = r1;
    }
}

// ---------------------------------------------------------------------------
// K1: gather -> split-bf16 HMMA -> LeakyReLU -> y + BN stats.
// 256 threads = 8 warps; warp w owns voxels [tile + 16w, tile + 16w + 16).
// ---------------------------------------------------------------------------
__global__ void __launch_bounds__(256, 2) k_conv(
    const float* __restrict__ feat,   // [N,32]
    const int*   __restrict__ nidx,   // [9,N]
    const void*  __restrict__ nmask,  // [9,N]
    float* __restrict__ out,          // [N,32]
    int N)
{
    __shared__ uint32_t wb0_s[9 * 4 * 4 * 32];
    __shared__ uint32_t wb1_s[9 * 4 * 4 * 32];
    __shared__ double   s_sum[32];
    __shared__ double   s_sumsq[32];

    const int tid = threadIdx.x;
    for (int i = tid; i < 1152; i += 256) {
        ((uint4*)wb0_s)[i] = ((const uint4*)g_wb0)[i];
        ((uint4*)wb1_s)[i] = ((const uint4*)g_wb1)[i];
    }
    if (tid < 32) { s_sum[tid] = 0.0; s_sumsq[tid] = 0.0; }
    __syncthreads();

    const int wid   = tid >> 5;
    const int lane  = tid & 31;
    const int tile  = blockIdx.x * 128;
    const int r0    = tile + wid * 16 + (lane >> 2);   // fragment row (voxel)
    const int r1    = r0 + 8;
    const int cbase = (lane & 3) * 2;                  // fragment col base
    const int mode  = g_mask_mode;
    const size_t Ns = (size_t)N;

    float acc[4][4];
#pragma unroll
    for (int nf = 0; nf < 4; nf++)
#pragma unroll
        for (int i = 0; i < 4; i++) acc[nf][i] = 0.0f;

#pragma unroll
    for (int k = 0; k < 9; k++) {
        const size_t kb = (size_t)k * Ns;
        float m0 = 0.0f, m1 = 0.0f;
        if (r0 < N) {
            if (mode == 0)      m0 = ((const float*)nmask)[kb + r0];
            else if (mode == 1) m0 = (float)((const int*)nmask)[kb + r0];
            else                m0 = (float)((const unsigned char*)nmask)[kb + r0];
        }
        if (r1 < N) {
            if (mode == 0)      m1 = ((const float*)nmask)[kb + r1];
            else if (mode == 1) m1 = (float)((const int*)nmask)[kb + r1];
            else                m1 = (float)((const unsigned char*)nmask)[kb + r1];
        }

        // gather: 4 float2 per row at channels cbase+{0,8,16,24}
        float2 p[8];
#pragma unroll
        for (int i = 0; i < 8; i++) p[i] = make_float2(0.0f, 0.0f);
        if (m0 != 0.0f) {
            const int j0 = nidx[kb + r0];
            const float2* f0 = (const float2*)(feat + (size_t)j0 * 32 + cbase);
            p[0] = f0[0]; p[1] = f0[4]; p[2] = f0[8]; p[3] = f0[12];
#pragma unroll
            for (int i = 0; i < 4; i++) { p[i].x *= m0; p[i].y *= m0; }
        }
        if (m1 != 0.0f) {
            const int j1 = nidx[kb + r1];
            const float2* f1 = (const float2*)(feat + (size_t)j1 * 32 + cbase);
            p[4] = f1[0]; p[5] = f1[4]; p[6] = f1[8]; p[7] = f1[12];
#pragma unroll
            for (int i = 4; i < 8; i++) { p[i].x *= m1; p[i].y *= m1; }
        }

        // split-convert to bf16 hi/lo packs
        uint32_t ah[8], al[8];
#pragma unroll
        for (int i = 0; i < 8; i++) {
            ah[i] = hi2(p[i].x, p[i].y);
            al[i] = lo2(ah[i], p[i].x, p[i].y);
        }

        // A fragments per k-chunk: {row r0 pair0, row r1 pair0, row r0 pair1, row r1 pair1}
        uint32_t Ahi0[4] = {ah[0], ah[4], ah[1], ah[5]};   // channels 0-15  (hi)
        uint32_t Ahi1[4] = {ah[2], ah[6], ah[3], ah[7]};   // channels 16-31 (hi)
        uint32_t Alo0[4] = {al[0], al[4], al[1], al[5]};   // channels 0-15  (lo)
        uint32_t Alo1[4] = {al[2], al[6], al[3], al[7]};   // channels 16-31 (lo)

        const int fb = k * 16;                              // frag base for this tap
#pragma unroll
        for (int nf = 0; nf < 4; nf++) {
            const int i0 = (fb + 0 * 4 + nf) * 32 + lane;   // hi W, k 0-15
            const int i1 = (fb + 1 * 4 + nf) * 32 + lane;   // hi W, k 16-31
            const int i2 = (fb + 2 * 4 + nf) * 32 + lane;   // lo W, k 0-15
            const int i3 = (fb + 3 * 4 + nf) * 32 + lane;   // lo W, k 16-31
            const uint32_t bh00 = wb0_s[i0], bh01 = wb1_s[i0];
            const uint32_t bh10 = wb0_s[i1], bh11 = wb1_s[i1];
            const uint32_t bl00 = wb0_s[i2], bl01 = wb1_s[i2];
            const uint32_t bl10 = wb0_s[i3], bl11 = wb1_s[i3];
            mma_bf16(acc[nf], Ahi0, bh00, bh01);   // hi * hiW
            mma_bf16(acc[nf], Ahi1, bh10, bh11);
            mma_bf16(acc[nf], Alo0, bh00, bh01);   // lo * hiW
            mma_bf16(acc[nf], Alo1, bh10, bh11);
            mma_bf16(acc[nf], Ahi0, bl00, bl01);   // hi * loW
            mma_bf16(acc[nf], Ahi1, bl10, bl11);
        }
    }

    // ---- LeakyReLU + store + BN partials ----
    float s8[8], z8[8];
#pragma unroll
    for (int i = 0; i < 8; i++) { s8[i] = 0.0f; z8[i] = 0.0f; }

#pragma unroll
    for (int nf = 0; nf < 4; nf++) {
        float y0 = acc[nf][0], y1 = acc[nf][1];   // row r0, cols col, col+1
        float y2 = acc[nf][2], y3 = acc[nf][3];   // row r1
        y0 = (y0 >= 0.0f) ? y0 : NEG_SLOPE * y0;
        y1 = (y1 >= 0.0f) ? y1 : NEG_SLOPE * y1;
        y2 = (y2 >= 0.0f) ? y2 : NEG_SLOPE * y2;
        y3 = (y3 >= 0.0f) ? y3 : NEG_SLOPE * y3;
        const int col = nf * 8 + cbase;
        if (r0 < N) *(float2*)(out + (size_t)r0 * 32 + col) = make_float2(y0, y1);
        else        { y0 = 0.0f; y1 = 0.0f; }
        if (r1 < N) *(float2*)(out + (size_t)r1 * 32 + col) = make_float2(y2, y3);
        else        { y2 = 0.0f; y3 = 0.0f; }
        s8[nf * 2 + 0] = y0 + y2;
        s8[nf * 2 + 1] = y1 + y3;
        z8[nf * 2 + 0] = y0 * y0 + y2 * y2;
        z8[nf * 2 + 1] = y1 * y1 + y3 * y3;
    }

    // reduce over lanes sharing (lane & 3): xor 4, 8, 16
#pragma unroll
    for (int off = 4; off < 32; off <<= 1) {
#pragma unroll
        for (int i = 0; i < 8; i++) {
            s8[i] += __shfl_xor_sync(FULLMASK, s8[i], off);
            z8[i] += __shfl_xor_sync(FULLMASK, z8[i], off);
        }
    }
    if (lane < 4) {
#pragma unroll
        for (int i = 0; i < 8; i++) {
            const int ch = (i >> 1) * 8 + (lane * 2) + (i & 1);
            atomicAdd(&s_sum[ch],   (double)s8[i]);
            atomicAdd(&s_sumsq[ch], (double)z8[i]);
        }
    }
    __syncthreads();
    if (tid < 32) {
        atomicAdd(&g_sum[tid],   s_sum[tid]);
        atomicAdd(&g_sumsq[tid], s_sumsq[tid]);
    }
}

// ---------------------------------------------------------------------------
// K2: finalize BN affine parameters.
// ---------------------------------------------------------------------------
__global__ void k_bn(const float* __restrict__ gamma,
                     const float* __restrict__ beta, int N) {
    int t = threadIdx.x;
    if (t < 32) {
        double invN = 1.0 / (double)N;
        double mean = g_sum[t] * invN;
        double var  = g_sumsq[t] * invN - mean * mean;
        float sc = gamma[t] * rsqrtf((float)var + BN_EPS);
        g_scale[t] = sc;
        g_bias[t]  = beta[t] - (float)mean * sc;
    }
}

// ---------------------------------------------------------------------------
// K3: in-place normalize, float4 vectorized.
// ---------------------------------------------------------------------------
__global__ void k_norm(float* __restrict__ out, long long total4) {
    long long i = (long long)blockIdx.x * blockDim.x + threadIdx.x;
    if (i >= total4) return;
    int cb = ((int)i & 7) * 4;
    float4 v = ((float4*)out)[i];
    v.x = v.x * g_scale[cb + 0] + g_bias[cb + 0];
    v.y = v.y * g_scale[cb + 1] + g_bias[cb + 1];
    v.z = v.z * g_scale[cb + 2] + g_bias[cb + 2];
    v.w = v.w * g_scale[cb + 3] + g_bias[cb + 3];
    ((float4*)out)[i] = v;
}

// ---------------------------------------------------------------------------
extern "C" void kernel_launch(void* const* d_in, const int* in_sizes, int n_in,
                              void* d_out, int out_size) {
    const float* feat  = (const float*)d_in[0];
    const float* wt    = (const float*)d_in[1];
    const float* gamma = (const float*)d_in[2];
    const float* beta  = (const float*)d_in[3];
    const int*   nidx  = (const int*)d_in[4];
    const void*  nmask = d_in[5];
    float* out = (float*)d_out;

    const int N = in_sizes[0] / 32;

    k_init<<<1, 64>>>((const unsigned int*)nmask);
    k_wprep<<<1, 256>>>(wt);

    const int tiles = (N + 127) / 128;
    k_conv<<<tiles, 256>>>(feat, nidx, nmask, out, N);

    k_bn<<<1, 32>>>(gamma, beta, N);

    const long long total4 = (long long)N * 8;
    const int nblocks = (int)((total4 + 255) / 256);
    k_norm<<<nblocks, 256>>>(out, total4);
}

// round 5
// speedup vs baseline: 1.8006x; 1.8006x over previous
#include <cuda_runtime.h>
#include <cuda_bf16.h>
#include <cstdint>

// ---------------------------------------------------------------------------
// Spconv (9-tap rulebook) + LeakyReLU + BatchNorm1d, fp32-accurate via
// split-precision bf16 HMMA (mma.sync.m16n8k16):
//   x = hi + lo;  x*w ~= hi*Whi + lo*Whi + hi*Wlo   (lo*lo dropped, ~2^-18)
// R5: hoisted idx/mask loads (full MLP), double-buffered gathers,
// mask-mult removed (0/1 gating), pad kernel so ncu captures k_conv.
// ---------------------------------------------------------------------------

#define FULLMASK 0xffffffffu
#define NEG_SLOPE 0.01f
#define BN_EPS 1e-5f

__device__ int      g_mask_mode;   // 0 = float32, 1 = int32, 2 = uint8/bool
__device__ double   g_sum[32];
__device__ double   g_sumsq[32];
__device__ float    g_scale[32];
__device__ float    g_bias[32];
// B fragments: frag fi = ((tap*4 + chunk)*4 + nfrag), per lane two u32 regs.
__device__ uint32_t g_wb0[9 * 4 * 4 * 32];
__device__ uint32_t g_wb1[9 * 4 * 4 * 32];

__device__ __forceinline__ uint32_t hi2(float e0, float e1) {
    uint32_t r;
    asm("cvt.rn.bf16x2.f32 %0, %1, %2;" : "=r"(r) : "f"(e1), "f"(e0));
    return r;
}
__device__ __forceinline__ uint32_t lo2(uint32_t h, float e0, float e1) {
    float h0 = __uint_as_float(h << 16);
    float h1 = __uint_as_float(h & 0xffff0000u);
    return hi2(e0 - h0, e1 - h1);
}

__device__ __forceinline__ void mma_bf16(float* d, const uint32_t* a,
                                         uint32_t b0, uint32_t b1) {
    asm volatile(
        "mma.sync.aligned.m16n8k16.row.col.f32.bf16.bf16.f32 "
        "{%0,%1,%2,%3}, {%4,%5,%6,%7}, {%8,%9}, {%0,%1,%2,%3};"
        : "+f"(d[0]), "+f"(d[1]), "+f"(d[2]), "+f"(d[3])
        : "r"(a[0]), "r"(a[1]), "r"(a[2]), "r"(a[3]), "r"(b0), "r"(b1));
}

// gather one tap's 16-channel slices for rows r0/r1 (j<0 => inactive => zeros)
__device__ __forceinline__ void gather_rows(const float* __restrict__ feat,
                                            int j0, int j1, int cbase,
                                            float2* p) {
#pragma unroll
    for (int i = 0; i < 8; i++) p[i] = make_float2(0.0f, 0.0f);
    if (j0 >= 0) {
        const float2* f0 = (const float2*)(feat + (size_t)j0 * 32 + cbase);
        p[0] = f0[0]; p[1] = f0[4]; p[2] = f0[8]; p[3] = f0[12];
    }
    if (j1 >= 0) {
        const float2* f1 = (const float2*)(feat + (size_t)j1 * 32 + cbase);
        p[4] = f1[0]; p[5] = f1[4]; p[6] = f1[8]; p[7] = f1[12];
    }
}

// ---------------------------------------------------------------------------
// K0: zero BN accumulators + detect mask dtype.
// ---------------------------------------------------------------------------
__global__ void k_init(const unsigned int* __restrict__ mask_words) {
    __shared__ int s_f32, s_u8;
    int t = threadIdx.x;
    if (t == 0) { s_f32 = 0; s_u8 = 0; }
    if (t < 32) { g_sum[t] = 0.0; g_sumsq[t] = 0.0; }
    __syncthreads();
    int f32 = 0, u8 = 0;
#pragma unroll
    for (int i = 0; i < 4; i++) {
        unsigned w = mask_words[t * 4 + i];
        if (w == 0x3F800000u) f32 = 1;
        else if (w & 0xFFFFFF00u) u8 = 1;
    }
    if (f32) atomicOr(&s_f32, 1);
    if (u8)  atomicOr(&s_u8, 1);
    __syncthreads();
    if (t == 0) g_mask_mode = s_f32 ? 0 : (s_u8 ? 2 : 1);
}

// ---------------------------------------------------------------------------
// Kw: build B fragments in per-lane HMMA layout (validated in R4).
// ---------------------------------------------------------------------------
__global__ void k_wprep(const float* __restrict__ wt) {
    for (int e = threadIdx.x; e < 9 * 4 * 4 * 32; e += blockDim.x) {
        int lane = e & 31;
        int fi   = e >> 5;
        int nf   = fi & 3;
        int j    = (fi >> 2) & 3;
        int t    = fi >> 4;
        int n    = nf * 8 + (lane >> 2);
        int kc   = (lane & 3) * 2 + (j & 1) * 16;
        float w0 = wt[(t * 32 + kc) * 32 + n];
        float w1 = wt[(t * 32 + kc + 1) * 32 + n];
        float w8 = wt[(t * 32 + kc + 8) * 32 + n];
        float w9 = wt[(t * 32 + kc + 9) * 32 + n];
        uint32_t r0, r1;
        if (j < 2) {
            r0 = hi2(w0, w1);
            r1 = hi2(w8, w9);
        } else {
            uint32_t h0 = hi2(w0, w1), h1 = hi2(w8, w9);
            r0 = lo2(h0, w0, w1);
            r1 = lo2(h1, w8, w9);
        }
        g_wb0[e] = r0;
        g_wb1[e] = r1;
    }
}

// pad kernel: occupies the profiler's capture slot so k_conv lands on slot 4
__global__ void k_pad() {}

// ---------------------------------------------------------------------------
// K1: gather -> split-bf16 HMMA -> LeakyReLU -> y + BN stats.
// 256 threads = 8 warps; warp w owns voxels [tile + 16w, tile + 16w + 16).
// ---------------------------------------------------------------------------
__global__ void __launch_bounds__(256, 2) k_conv(
    const float* __restrict__ feat,   // [N,32]
    const int*   __restrict__ nidx,   // [9,N]
    const void*  __restrict__ nmask,  // [9,N]
    float* __restrict__ out,          // [N,32]
    int N)
{
    __shared__ uint32_t wb0_s[9 * 4 * 4 * 32];
    __shared__ uint32_t wb1_s[9 * 4 * 4 * 32];
    __shared__ double   s_sum[32];
    __shared__ double   s_sumsq[32];

    const int tid = threadIdx.x;
    for (int i = tid; i < 1152; i += 256) {
        ((uint4*)wb0_s)[i] = ((const uint4*)g_wb0)[i];
        ((uint4*)wb1_s)[i] = ((const uint4*)g_wb1)[i];
    }
    if (tid < 32) { s_sum[tid] = 0.0; s_sumsq[tid] = 0.0; }
    __syncthreads();

    const int wid   = tid >> 5;
    const int lane  = tid & 31;
    const int tile  = blockIdx.x * 128;
    const int r0    = tile + wid * 16 + (lane >> 2);
    const int r1    = r0 + 8;
    const int cbase = (lane & 3) * 2;
    const int mode  = g_mask_mode;
    const size_t Ns = (size_t)N;
    const bool v0 = (r0 < N), v1 = (r1 < N);

    // ---- hoist idx + mask for all 9 taps (independent loads, full MLP) ----
    int j0[9], j1[9];
    {
        int i0[9], i1[9];
#pragma unroll
        for (int k = 0; k < 9; k++) {
            const size_t kb = (size_t)k * Ns;
            i0[k] = v0 ? nidx[kb + r0] : 0;
            i1[k] = v1 ? nidx[kb + r1] : 0;
        }
        if (mode == 0) {
            const float* mp = (const float*)nmask;
#pragma unroll
            for (int k = 0; k < 9; k++) {
                const size_t kb = (size_t)k * Ns;
                j0[k] = (v0 && mp[kb + r0] != 0.0f) ? i0[k] : -1;
                j1[k] = (v1 && mp[kb + r1] != 0.0f) ? i1[k] : -1;
            }
        } else if (mode == 1) {
            const int* mp = (const int*)nmask;
#pragma unroll
            for (int k = 0; k < 9; k++) {
                const size_t kb = (size_t)k * Ns;
                j0[k] = (v0 && mp[kb + r0] != 0) ? i0[k] : -1;
                j1[k] = (v1 && mp[kb + r1] != 0) ? i1[k] : -1;
            }
        } else {
            const unsigned char* mp = (const unsigned char*)nmask;
#pragma unroll
            for (int k = 0; k < 9; k++) {
                const size_t kb = (size_t)k * Ns;
                j0[k] = (v0 && mp[kb + r0] != 0) ? i0[k] : -1;
                j1[k] = (v1 && mp[kb + r1] != 0) ? i1[k] : -1;
            }
        }
    }

    float acc[4][4];
#pragma unroll
    for (int nf = 0; nf < 4; nf++)
#pragma unroll
        for (int i = 0; i < 4; i++) acc[nf][i] = 0.0f;

    // ---- main loop: double-buffered gather, cvt, 24 MMAs per tap ----
    float2 pc[8], pn[8];
    gather_rows(feat, j0[0], j1[0], cbase, pc);

#pragma unroll
    for (int k = 0; k < 9; k++) {
        if (k < 8) gather_rows(feat, j0[k + 1], j1[k + 1], cbase, pn);

        uint32_t ah[8], al[8];
#pragma unroll
        for (int i = 0; i < 8; i++) {
            ah[i] = hi2(pc[i].x, pc[i].y);
            al[i] = lo2(ah[i], pc[i].x, pc[i].y);
        }

        uint32_t Ahi0[4] = {ah[0], ah[4], ah[1], ah[5]};
        uint32_t Ahi1[4] = {ah[2], ah[6], ah[3], ah[7]};
        uint32_t Alo0[4] = {al[0], al[4], al[1], al[5]};
        uint32_t Alo1[4] = {al[2], al[6], al[3], al[7]};

        const int fb = k * 16;
#pragma unroll
        for (int nf = 0; nf < 4; nf++) {
            const int i0 = (fb + 0 * 4 + nf) * 32 + lane;
            const int i1 = (fb + 1 * 4 + nf) * 32 + lane;
            const int i2 = (fb + 2 * 4 + nf) * 32 + lane;
            const int i3 = (fb + 3 * 4 + nf) * 32 + lane;
            const uint32_t bh00 = wb0_s[i0], bh01 = wb1_s[i0];
            const uint32_t bh10 = wb0_s[i1], bh11 = wb1_s[i1];
            const uint32_t bl00 = wb0_s[i2], bl01 = wb1_s[i2];
            const uint32_t bl10 = wb0_s[i3], bl11 = wb1_s[i3];
            mma_bf16(acc[nf], Ahi0, bh00, bh01);
            mma_bf16(acc[nf], Ahi1, bh10, bh11);
            mma_bf16(acc[nf], Alo0, bh00, bh01);
            mma_bf16(acc[nf], Alo1, bh10, bh11);
            mma_bf16(acc[nf], Ahi0, bl00, bl01);
            mma_bf16(acc[nf], Ahi1, bl10, bl11);
        }

#pragma unroll
        for (int i = 0; i < 8; i++) pc[i] = pn[i];
    }

    // ---- LeakyReLU + store + BN partials ----
    float s8[8], z8[8];
#pragma unroll
    for (int i = 0; i < 8; i++) { s8[i] = 0.0f; z8[i] = 0.0f; }

#pragma unroll
    for (int nf = 0; nf < 4; nf++) {
        float y0 = acc[nf][0], y1 = acc[nf][1];
        float y2 = acc[nf][2], y3 = acc[nf][3];
        y0 = (y0 >= 0.0f) ? y0 : NEG_SLOPE * y0;
        y1 = (y1 >= 0.0f) ? y1 : NEG_SLOPE * y1;
        y2 = (y2 >= 0.0f) ? y2 : NEG_SLOPE * y2;
        y3 = (y3 >= 0.0f) ? y3 : NEG_SLOPE * y3;
        const int col = nf * 8 + cbase;
        if (v0) *(float2*)(out + (size_t)r0 * 32 + col) = make_float2(y0, y1);
        else    { y0 = 0.0f; y1 = 0.0f; }
        if (v1) *(float2*)(out + (size_t)r1 * 32 + col) = make_float2(y2, y3);
        else    { y2 = 0.0f; y3 = 0.0f; }
        s8[nf * 2 + 0] = y0 + y2;
        s8[nf * 2 + 1] = y1 + y3;
        z8[nf * 2 + 0] = y0 * y0 + y2 * y2;
        z8[nf * 2 + 1] = y1 * y1 + y3 * y3;
    }

#pragma unroll
    for (int off = 4; off < 32; off <<= 1) {
#pragma unroll
        for (int i = 0; i < 8; i++) {
            s8[i] += __shfl_xor_sync(FULLMASK, s8[i], off);
            z8[i] += __shfl_xor_sync(FULLMASK, z8[i], off);
        }
    }
    if (lane < 4) {
#pragma unroll
        for (int i = 0; i < 8; i++) {
            const int ch = (i >> 1) * 8 + (lane * 2) + (i & 1);
            atomicAdd(&s_sum[ch],   (double)s8[i]);
            atomicAdd(&s_sumsq[ch], (double)z8[i]);
        }
    }
    __syncthreads();
    if (tid < 32) {
        atomicAdd(&g_sum[tid],   s_sum[tid]);
        atomicAdd(&g_sumsq[tid], s_sumsq[tid]);
    }
}

// ---------------------------------------------------------------------------
// K2: finalize BN affine parameters.
// ---------------------------------------------------------------------------
__global__ void k_bn(const float* __restrict__ gamma,
                     const float* __restrict__ beta, int N) {
    int t = threadIdx.x;
    if (t < 32) {
        double invN = 1.0 / (double)N;
        double mean = g_sum[t] * invN;
        double var  = g_sumsq[t] * invN - mean * mean;
        float sc = gamma[t] * rsqrtf((float)var + BN_EPS);
        g_scale[t] = sc;
        g_bias[t]  = beta[t] - (float)mean * sc;
    }
}

// ---------------------------------------------------------------------------
// K3: in-place normalize, float4 vectorized.
// ---------------------------------------------------------------------------
__global__ void k_norm(float* __restrict__ out, long long total4) {
    long long i = (long long)blockIdx.x * blockDim.x + threadIdx.x;
    if (i >= total4) return;
    int cb = ((int)i & 7) * 4;
    float4 v = ((float4*)out)[i];
    v.x = v.x * g_scale[cb + 0] + g_bias[cb + 0];
    v.y = v.y * g_scale[cb + 1] + g_bias[cb + 1];
    v.z = v.z * g_scale[cb + 2] + g_bias[cb + 2];
    v.w = v.w * g_scale[cb + 3] + g_bias[cb + 3];
    ((float4*)out)[i] = v;
}

// ---------------------------------------------------------------------------
extern "C" void kernel_launch(void* const* d_in, const int* in_sizes, int n_in,
                              void* d_out, int out_size) {
    const float* feat  = (const float*)d_in[0];
    const float* wt    = (const float*)d_in[1];
    const float* gamma = (const float*)d_in[2];
    const float* beta  = (const float*)d_in[3];
    const int*   nidx  = (const int*)d_in[4];
    const void*  nmask = d_in[5];
    float* out = (float*)d_out;

    const int N = in_sizes[0] / 32;

    k_init<<<1, 64>>>((const unsigned int*)nmask);   // launch 1
    k_wprep<<<1, 256>>>(wt);                         // launch 2
    k_pad<<<1, 32>>>();                              // launch 3 (slot filler)

    const int tiles = (N + 127) / 128;
    k_conv<<<tiles, 256>>>(feat, nidx, nmask, out, N);   // launch 4 -> profiled

    k_bn<<<1, 32>>>(gamma, beta, N);

    const long long total4 = (long long)N * 8;
    const int nblocks = (int)((total4 + 255) / 256);
    k_norm<<<nblocks, 256>>>(out, total4);
}